// round 6
// baseline (speedup 1.0000x reference)
#include <cuda_runtime.h>

#define BATCH 16
#define CIN   512
#define MID   128
#define GRP   4
#define H     56
#define W     56
#define HW    (H*W)
#define MH    7
#define MW    7
#define EPSV  1e-5f

// Scratch: post-mask intermediate activations (device globals, no alloc).
__device__ float g_y1[BATCH * MID * HW];   // relu(bn1(conv1(x*m))) * m
__device__ float g_y2[BATCH * MID * HW];   // relu(bn2(conv2(y1))) * m

// ---------------------------------------------------------------------------
// Kernel 1: 1x1 grouped conv (512->128) + BN + ReLU, 8x8 tile, ONE group/CTA.
// 256 thr split-K: kh = t>>7 handles ic half [kh*64, kh*64+64).
// Within half: ocq = (t&127)>>4 (4 oc), pxq = t&15 (4 px).
// Whole x tile (128 ic x 64 px = 32 KB) staged up front -> no mid-loop syncs.
// Per ic: LDS.128(x) + LDS.128(w) + 16 FFMA. Final 8 KB smem reduction.
// ---------------------------------------------------------------------------
#define K1_OFF_W 0
#define K1_OFF_X (128 * 36)                       // floats
#define K1_SMEM  ((128 * 36 + 128 * 64) * 4)      // 51200 B

__global__ __launch_bounds__(256) void k1_conv1(
    const float* __restrict__ x, const float* __restrict__ mask,
    const float* __restrict__ w1,
    const float* __restrict__ g1, const float* __restrict__ b1,
    const float* __restrict__ m1, const float* __restrict__ v1)
{
    const int bh = blockIdx.x / 7, bw = blockIdx.x % 7;
    const int g = blockIdx.y, b = blockIdx.z;
    const int h0 = bh * 8, w0 = bw * 8;
    const int t = threadIdx.x;
    const int kh = t >> 7;              // ic half
    const int t7 = t & 127;
    const int ocq = t7 >> 4;            // [0,8): 4-oc slice
    const int pxq = t & 15;             // [0,16): 4-px quad
    const int r = pxq >> 1, cst = (pxq & 1) * 4;

    const float m = mask[((b * GRP + g) * MH + bh) * MW + bw];

    if (m == 0.0f) {
        const float4 z = make_float4(0.f, 0.f, 0.f, 0.f);
        // 256 thr x 2 stores cover 64 px x 32 oc / 4
        #pragma unroll
        for (int j = 0; j < 2; j++) {
            int id = t + j * 256;           // [0,512)
            int oc = id >> 4, p4 = id & 15;
            int rr = p4 >> 1, c2 = (p4 & 1) * 4;
            *(float4*)&g_y1[((b * MID + g * 32 + oc) * H + h0 + rr) * W + w0 + c2] = z;
        }
        return;
    }

    extern __shared__ float sm1[];
    float*  w_s = sm1 + K1_OFF_W;               // [ic][oc pad36]
    float4* x4  = (float4*)(sm1 + K1_OFF_X);    // [ic][pxq]

    // weights: w1[(g*32+oc)*128 + ic] -> w_s[ic*36 + oc]
    const float* w1g = w1 + (g * 32) * 128;
    #pragma unroll
    for (int i = t; i < 32 * 128; i += 256)
        w_s[(i & 127) * 36 + (i >> 7)] = w1g[i];

    // whole x tile: 128 ic x 16 quads, 8 float4 per thread
    #pragma unroll
    for (int j = 0; j < 8; j++) {
        int id = t + j * 256;               // [0,2048)
        int ic = id >> 4, p4 = id & 15;
        int rr = p4 >> 1, c2 = (p4 & 1) * 4;
        x4[ic * 16 + p4] = *(const float4*)&x[
            ((long)(b * CIN + g * 128 + ic) * H + h0 + rr) * W + w0 + c2];
    }
    __syncthreads();

    float acc[4][4];
    #pragma unroll
    for (int k = 0; k < 4; k++)
        #pragma unroll
        for (int q = 0; q < 4; q++) acc[k][q] = 0.0f;

    const int icbase = kh * 64;
    #pragma unroll 8
    for (int icc = 0; icc < 64; icc++) {
        const int ic = icbase + icc;
        float4 xv = x4[ic * 16 + pxq];
        float4 wv = *(const float4*)&w_s[ic * 36 + ocq * 4];
        acc[0][0] += wv.x * xv.x; acc[0][1] += wv.x * xv.y;
        acc[0][2] += wv.x * xv.z; acc[0][3] += wv.x * xv.w;
        acc[1][0] += wv.y * xv.x; acc[1][1] += wv.y * xv.y;
        acc[1][2] += wv.y * xv.z; acc[1][3] += wv.y * xv.w;
        acc[2][0] += wv.z * xv.x; acc[2][1] += wv.z * xv.y;
        acc[2][2] += wv.z * xv.z; acc[2][3] += wv.z * xv.w;
        acc[3][0] += wv.w * xv.x; acc[3][1] += wv.w * xv.y;
        acc[3][2] += wv.w * xv.z; acc[3][3] += wv.w * xv.w;
    }

    // split-K reduction: kh=1 writes partials into (now dead) x region
    __syncthreads();
    float4* red = (float4*)(sm1 + K1_OFF_X);    // [t7][4]
    if (kh == 1) {
        #pragma unroll
        for (int k = 0; k < 4; k++)
            red[t7 * 4 + k] = make_float4(acc[k][0], acc[k][1], acc[k][2], acc[k][3]);
    }
    __syncthreads();
    if (kh == 0) {
        #pragma unroll
        for (int k = 0; k < 4; k++) {
            float4 p = red[t7 * 4 + k];
            int gc = g * 32 + ocq * 4 + k;
            float sc = g1[gc] * rsqrtf(v1[gc] + EPSV);
            float bi = b1[gc] - m1[gc] * sc;
            float4 v;
            v.x = fmaxf((acc[k][0] + p.x) * sc + bi, 0.0f);
            v.y = fmaxf((acc[k][1] + p.y) * sc + bi, 0.0f);
            v.z = fmaxf((acc[k][2] + p.z) * sc + bi, 0.0f);
            v.w = fmaxf((acc[k][3] + p.w) * sc + bi, 0.0f);
            *(float4*)&g_y1[((b * MID + gc) * H + h0 + r) * W + w0 + cst] = v;
        }
    }
}

// ---------------------------------------------------------------------------
// Kernel 2: 3x3 grouped conv (128->128, pad 1) + BN + ReLU + mask.
// 256 thr split-K: kh = t>>7 handles ic half [kh*16, kh*16+16).
// Within half: pxq = (t&127)>>3 (4 px), ocq = t&7 (4 oc).
// Halo + full weight slab staged once; final reduction aliases halo.
// Per ic: 18 scalar LDS + 9 LDS.128 + 144 FFMA.
// ---------------------------------------------------------------------------
#define K2_HALO   3200                     // 32*100 floats
#define K2_WSLAB  (32 * 9 * 36)            // [ic][tap][oc pad36] floats
#define K2_SMEM   ((K2_HALO + K2_WSLAB) * 4)

__global__ __launch_bounds__(256) void k2_conv2(
    const float* __restrict__ mask,
    const float* __restrict__ w2,
    const float* __restrict__ g2, const float* __restrict__ b2,
    const float* __restrict__ m2, const float* __restrict__ v2)
{
    const int bh = blockIdx.x / 7, bw = blockIdx.x % 7;
    const int g = blockIdx.y, b = blockIdx.z;
    const int h0 = bh * 8, w0 = bw * 8;
    const int t = threadIdx.x;
    const int kh = t >> 7;
    const int t7 = t & 127;
    const int pxq = t7 >> 3;               // [0,16): 4 px
    const int ocq = t & 7;                 // [0,8): 4-oc slice
    const int r = pxq >> 1, cst = (pxq & 1) * 4;

    const float m = mask[((b * GRP + g) * MH + bh) * MW + bw];

    if (m == 0.0f) {
        const float4 z = make_float4(0.f, 0.f, 0.f, 0.f);
        #pragma unroll
        for (int j = 0; j < 2; j++) {
            int id = t + j * 256;
            int oc = id >> 4, p4 = id & 15;
            int rr = p4 >> 1, c2 = (p4 & 1) * 4;
            *(float4*)&g_y2[((b * MID + g * 32 + oc) * H + h0 + rr) * W + w0 + c2] = z;
        }
        return;
    }

    extern __shared__ float sm2[];
    float* in_s = sm2;                     // [32][100]
    float* w_s  = sm2 + K2_HALO;           // [ic][tap][oc]: ic*324 + tap*36 + oc

    // halo (y1 already post-mask; zero-pad borders)
    for (int i = t; i < 32 * 100; i += 256) {
        int ic = i / 100, p = i % 100;
        int rr = h0 + p / 10 - 1, c2 = w0 + p % 10 - 1;
        float v = 0.0f;
        if (rr >= 0 && rr < H && c2 >= 0 && c2 < W)
            v = g_y1[((b * MID + g * 32 + ic) * H + rr) * W + c2];
        in_s[ic * 100 + p] = v;
    }
    // weights: w2[(g*32+oc)*288 + ic*9 + kk] -> w_s[ic][kk][oc]
    const float* w2g = w2 + (g * 32) * 288;
    for (int i = t; i < 32 * 288; i += 256) {
        int oc = i / 288, rem = i % 288;
        int ic = rem / 9, kk = rem % 9;
        w_s[ic * 324 + kk * 36 + oc] = w2g[i];
    }
    __syncthreads();

    float acc[4][4];
    #pragma unroll
    for (int k = 0; k < 4; k++)
        #pragma unroll
        for (int q = 0; q < 4; q++) acc[k][q] = 0.0f;

    const int icbase = kh * 16;
    #pragma unroll 2
    for (int icc = 0; icc < 16; icc++) {
        const int ic = icbase + icc;
        float xr[3][6];
        #pragma unroll
        for (int kr = 0; kr < 3; kr++)
            #pragma unroll
            for (int j = 0; j < 6; j++)
                xr[kr][j] = in_s[ic * 100 + (r + kr) * 10 + cst + j];
        #pragma unroll
        for (int kr = 0; kr < 3; kr++) {
            #pragma unroll
            for (int kc = 0; kc < 3; kc++) {
                float4 wv = *(const float4*)&w_s[ic * 324 + (kr * 3 + kc) * 36 + ocq * 4];
                #pragma unroll
                for (int q = 0; q < 4; q++) {
                    float xv = xr[kr][q + kc];
                    acc[0][q] += wv.x * xv;
                    acc[1][q] += wv.y * xv;
                    acc[2][q] += wv.z * xv;
                    acc[3][q] += wv.w * xv;
                }
            }
        }
    }

    // split-K reduction (aliases halo region)
    __syncthreads();
    float4* red = (float4*)sm2;            // [t7][4]
    if (kh == 1) {
        #pragma unroll
        for (int k = 0; k < 4; k++)
            red[t7 * 4 + k] = make_float4(acc[k][0], acc[k][1], acc[k][2], acc[k][3]);
    }
    __syncthreads();
    if (kh == 0) {
        #pragma unroll
        for (int k = 0; k < 4; k++) {
            float4 p = red[t7 * 4 + k];
            int gc = g * 32 + ocq * 4 + k;
            float sc = g2[gc] * rsqrtf(v2[gc] + EPSV);
            float bi = b2[gc] - m2[gc] * sc;
            float4 v;
            v.x = fmaxf((acc[k][0] + p.x) * sc + bi, 0.0f);
            v.y = fmaxf((acc[k][1] + p.y) * sc + bi, 0.0f);
            v.z = fmaxf((acc[k][2] + p.z) * sc + bi, 0.0f);
            v.w = fmaxf((acc[k][3] + p.w) * sc + bi, 0.0f);
            *(float4*)&g_y2[((b * MID + gc) * H + h0 + r) * W + w0 + cst] = v;
        }
    }
}

// ---------------------------------------------------------------------------
// Kernel 3: 1x1 grouped conv (128->512) + BN + residual + ReLU.
// Thread: 4 px x 8 oc. Per ic: LDS.128(x) + 2x LDS.128(w) + 32 FFMA.
// mask==0 -> out = relu(bias3 + x).
// ---------------------------------------------------------------------------
__global__ __launch_bounds__(256) void k3_conv3(
    const float* __restrict__ x, const float* __restrict__ mask,
    const float* __restrict__ w3,
    const float* __restrict__ g3, const float* __restrict__ b3,
    const float* __restrict__ m3, const float* __restrict__ v3,
    float* __restrict__ out)
{
    const int bh = blockIdx.x / 7, bw = blockIdx.x % 7;
    const int g = blockIdx.y, b = blockIdx.z;
    const int h0 = bh * 8, w0 = bw * 8;
    const int t = threadIdx.x;
    const int pxq = t >> 4, ocp = t & 15;
    const int r = pxq >> 1, cst = (pxq & 1) * 4;

    const float m = mask[((b * GRP + g) * MH + bh) * MW + bw];

    if (m == 0.0f) {
        #pragma unroll
        for (int k = 0; k < 8; k++) {
            int gc = g * 128 + ocp * 8 + k;
            float sc = g3[gc] * rsqrtf(v3[gc] + EPSV);
            float bi = b3[gc] - m3[gc] * sc;
            long idx = ((long)(b * CIN + gc) * H + h0 + r) * W + w0 + cst;
            float4 xv = *(const float4*)&x[idx];
            float4 v;
            v.x = fmaxf(bi + xv.x, 0.0f);
            v.y = fmaxf(bi + xv.y, 0.0f);
            v.z = fmaxf(bi + xv.z, 0.0f);
            v.w = fmaxf(bi + xv.w, 0.0f);
            *(float4*)&out[idx] = v;
        }
        return;
    }

    __shared__ float  w_s[32][132];     // [ic][oc], padded
    __shared__ float4 y_s[32][16];      // [ic][pxq]

    const float* w3g = w3 + (g * 128) * 32;     // [oc=128][ic=32]
    #pragma unroll
    for (int i = t; i < 128 * 32; i += 256)
        w_s[i & 31][i >> 5] = w3g[i];
    #pragma unroll
    for (int j = 0; j < 2; j++) {
        int i = t + j * 256;
        int ic = i >> 4, p4 = i & 15;
        int rr = p4 >> 1, c2 = (p4 & 1) * 4;
        y_s[ic][p4] = *(const float4*)&g_y2[
            ((b * MID + g * 32 + ic) * H + h0 + rr) * W + w0 + c2];
    }
    __syncthreads();

    float acc[8][4];
    #pragma unroll
    for (int k = 0; k < 8; k++)
        #pragma unroll
        for (int q = 0; q < 4; q++) acc[k][q] = 0.0f;

    #pragma unroll 4
    for (int ic = 0; ic < 32; ic++) {
        float4 xv = y_s[ic][pxq];
        const float* wr = &w_s[ic][ocp * 8];
        float4 wa = *(const float4*)wr;
        float4 wb = *(const float4*)(wr + 4);
        float wk[8] = {wa.x, wa.y, wa.z, wa.w, wb.x, wb.y, wb.z, wb.w};
        #pragma unroll
        for (int k = 0; k < 8; k++) {
            acc[k][0] += wk[k] * xv.x;
            acc[k][1] += wk[k] * xv.y;
            acc[k][2] += wk[k] * xv.z;
            acc[k][3] += wk[k] * xv.w;
        }
    }

    #pragma unroll
    for (int k = 0; k < 8; k++) {
        int gc = g * 128 + ocp * 8 + k;
        float sc = g3[gc] * rsqrtf(v3[gc] + EPSV);
        float bi = b3[gc] - m3[gc] * sc;
        long idx = ((long)(b * CIN + gc) * H + h0 + r) * W + w0 + cst;
        float4 xv = *(const float4*)&x[idx];
        float4 v;
        v.x = fmaxf(acc[k][0] * sc + bi + xv.x, 0.0f);
        v.y = fmaxf(acc[k][1] * sc + bi + xv.y, 0.0f);
        v.z = fmaxf(acc[k][2] * sc + bi + xv.z, 0.0f);
        v.w = fmaxf(acc[k][3] * sc + bi + xv.w, 0.0f);
        *(float4*)&out[idx] = v;
    }
}

// ---------------------------------------------------------------------------
extern "C" void kernel_launch(void* const* d_in, const int* in_sizes, int n_in,
                              void* d_out, int out_size)
{
    const float* x    = (const float*)d_in[0];
    const float* mask = (const float*)d_in[1];
    const float* w1   = (const float*)d_in[2];
    const float* g1   = (const float*)d_in[3];
    const float* b1   = (const float*)d_in[4];
    const float* m1   = (const float*)d_in[5];
    const float* v1   = (const float*)d_in[6];
    const float* w2   = (const float*)d_in[7];
    const float* g2   = (const float*)d_in[8];
    const float* b2   = (const float*)d_in[9];
    const float* m2   = (const float*)d_in[10];
    const float* v2   = (const float*)d_in[11];
    const float* w3   = (const float*)d_in[12];
    const float* g3   = (const float*)d_in[13];
    const float* b3   = (const float*)d_in[14];
    const float* m3   = (const float*)d_in[15];
    const float* v3   = (const float*)d_in[16];
    float* out = (float*)d_out;

    cudaFuncSetAttribute(k1_conv1, cudaFuncAttributeMaxDynamicSharedMemorySize, K1_SMEM);
    cudaFuncSetAttribute(k2_conv2, cudaFuncAttributeMaxDynamicSharedMemorySize, K2_SMEM);

    dim3 grid(49, GRP, BATCH);
    k1_conv1<<<grid, 256, K1_SMEM>>>(x, mask, w1, g1, b1, m1, v1);
    k2_conv2<<<grid, 256, K2_SMEM>>>(mask, w2, g2, b2, m2, v2);
    k3_conv3<<<grid, 256>>>(x, mask, w3, g3, b3, m3, v3, out);
}

// round 7
// speedup vs baseline: 1.1450x; 1.1450x over previous
#include <cuda_runtime.h>

#define BATCH 16
#define CIN   512
#define MID   128
#define GRP   4
#define H     56
#define W     56
#define HW    (H*W)
#define MH    7
#define MW    7
#define EPSV  1e-5f

// Scratch (device globals, no alloc).
__device__ float g_y1[BATCH * MID * HW];   // relu(bn1(conv1(x*m))) * m
// Pre-transposed weights:
__device__ float tw1[4 * 128 * 32];        // [g][ic][oc]
__device__ float tw2[4 * 32 * 9 * 32];     // [g][ic][tap][oc]
__device__ float tw3[4 * 32 * 128];        // [g][ic][oc]

// ---------------------------------------------------------------------------
// Setup: transpose weights into GEMM-friendly layouts (linear smem copies).
// ---------------------------------------------------------------------------
__global__ void setup_tw(const float* __restrict__ w1,
                         const float* __restrict__ w2,
                         const float* __restrict__ w3)
{
    int i = blockIdx.x * 256 + threadIdx.x;
    if (i < 16384) {                       // tw1[g][ic][oc32]
        int g = i >> 12, r = i & 4095, ic = r >> 5, oc = r & 31;
        tw1[i] = w1[(g * 32 + oc) * 128 + ic];
    }
    if (i < 36864) {                       // tw2[g][ic][kk][oc32]
        int g = i / 9216, r = i % 9216, ic = r / 288, r2 = r % 288;
        int kk = r2 >> 5, oc = r2 & 31;
        tw2[i] = w2[(g * 32 + oc) * 288 + ic * 9 + kk];
    }
    if (i < 16384) {                       // tw3[g][ic][oc128]
        int g = i >> 12, r = i & 4095, ic = r >> 7, oc = r & 127;
        tw3[i] = w3[(g * 128 + oc) * 32 + ic];
    }
}

// ---------------------------------------------------------------------------
// Kernel 1: 1x1 grouped conv (512->128) + BN + ReLU (+mask), 8x8 tile.
// CTA = (tile, group-pair, batch), 256 thr. Thread = 4px x 4oc.
// (R5 structure — measured 44.9us — with float4 weight fill from tw1.)
// ---------------------------------------------------------------------------
__global__ __launch_bounds__(256) void k1_conv1(
    const float* __restrict__ x, const float* __restrict__ mask,
    const float* __restrict__ g1, const float* __restrict__ b1,
    const float* __restrict__ m1, const float* __restrict__ v1)
{
    const int bh = blockIdx.x / 7, bw = blockIdx.x % 7;
    const int gp = blockIdx.y, b = blockIdx.z;      // group pair (0/1)
    const int h0 = bh * 8, w0 = bw * 8;
    const int t = threadIdx.x;
    const int ocq = t >> 4;            // [0,16): 4-oc slice within 64 oc
    const int pxq = t & 15;            // [0,16): 4-px quad
    const int r = pxq >> 1, cst = (pxq & 1) * 4;

    const float m0 = mask[((b * GRP + gp * 2 + 0) * MH + bh) * MW + bw];
    const float m1v = mask[((b * GRP + gp * 2 + 1) * MH + bh) * MW + bw];

    if (m0 == 0.0f && m1v == 0.0f) {
        const float4 z = make_float4(0.f, 0.f, 0.f, 0.f);
        #pragma unroll
        for (int k = 0; k < 4; k++) {
            int gc = gp * 64 + ocq * 4 + k;
            *(float4*)&g_y1[((b * MID + gc) * H + h0 + r) * W + w0 + cst] = z;
        }
        return;
    }

    __shared__ float  w_s[128][68];     // [ic][oc 0..63], pad 68
    __shared__ float4 x_s[2][32][16];   // [grp][ic-in-chunk][pxq]

    // weight fill: tw1 slabs for groups gp*2, gp*2+1 are contiguous (4096 fl each)
    {
        const float4* src = (const float4*)(tw1 + gp * 2 * 4096);
        float4* dst = (float4*)&w_s[0][0];          // row stride 17 float4
        #pragma unroll
        for (int j = 0; j < 8; j++) {
            int i = t + j * 256;        // [0,2048)
            int gg = i >> 10, rem = i & 1023;
            int ic = rem >> 3, oc4 = rem & 7;
            dst[ic * 17 + gg * 8 + oc4] = src[i];
        }
    }

    const int myg = ocq >> 3;               // warp-uniform group
    const bool active = (myg ? m1v : m0) != 0.0f;

    float4 pre[4];
    const float* xptr[4];
    bool  lact[4];
    int   sic[4], sp4v[4], sgg[4];
    #pragma unroll
    for (int j = 0; j < 4; j++) {
        int id = t + j * 256;
        int gg = id >> 9, ic = (id >> 4) & 31, p4 = id & 15;
        int rr = p4 >> 1, c2 = (p4 & 1) * 4;
        sgg[j] = gg; sic[j] = ic; sp4v[j] = p4;
        lact[j] = (gg ? m1v : m0) != 0.0f;
        xptr[j] = x + ((long)(b * CIN + (gp * 2 + gg) * 128 + ic) * H + h0 + rr) * W + w0 + c2;
    }

    #pragma unroll
    for (int j = 0; j < 4; j++) {
        float4 v = make_float4(0.f, 0.f, 0.f, 0.f);
        if (lact[j]) v = *(const float4*)xptr[j];
        x_s[sgg[j]][sic[j]][sp4v[j]] = v;
    }
    __syncthreads();

    float acc[4][4];
    #pragma unroll
    for (int k = 0; k < 4; k++)
        #pragma unroll
        for (int q = 0; q < 4; q++) acc[k][q] = 0.0f;

    for (int cc = 0; cc < 4; cc++) {        // 4 chunks of 32 ic
        if (cc < 3) {
            #pragma unroll
            for (int j = 0; j < 4; j++) {
                pre[j] = make_float4(0.f, 0.f, 0.f, 0.f);
                if (lact[j]) pre[j] = *(const float4*)(xptr[j] + (long)(cc + 1) * 32 * HW);
            }
        }
        if (active) {
            #pragma unroll
            for (int icc = 0; icc < 32; icc++) {
                float4 xv = x_s[myg][icc][pxq];
                float4 wv = *(const float4*)&w_s[cc * 32 + icc][ocq * 4];
                acc[0][0] += wv.x * xv.x; acc[0][1] += wv.x * xv.y;
                acc[0][2] += wv.x * xv.z; acc[0][3] += wv.x * xv.w;
                acc[1][0] += wv.y * xv.x; acc[1][1] += wv.y * xv.y;
                acc[1][2] += wv.y * xv.z; acc[1][3] += wv.y * xv.w;
                acc[2][0] += wv.z * xv.x; acc[2][1] += wv.z * xv.y;
                acc[2][2] += wv.z * xv.z; acc[2][3] += wv.z * xv.w;
                acc[3][0] += wv.w * xv.x; acc[3][1] += wv.w * xv.y;
                acc[3][2] += wv.w * xv.z; acc[3][3] += wv.w * xv.w;
            }
        }
        if (cc < 3) {
            __syncthreads();
            #pragma unroll
            for (int j = 0; j < 4; j++)
                x_s[sgg[j]][sic[j]][sp4v[j]] = pre[j];
            __syncthreads();
        }
    }

    const float mymask = myg ? m1v : m0;
    #pragma unroll
    for (int k = 0; k < 4; k++) {
        int gc = gp * 64 + ocq * 4 + k;
        float sc = g1[gc] * rsqrtf(v1[gc] + EPSV);
        float bi = b1[gc] - m1[gc] * sc;
        float4 v;
        if (mymask != 0.0f) {
            v.x = fmaxf(acc[k][0] * sc + bi, 0.0f);
            v.y = fmaxf(acc[k][1] * sc + bi, 0.0f);
            v.z = fmaxf(acc[k][2] * sc + bi, 0.0f);
            v.w = fmaxf(acc[k][3] * sc + bi, 0.0f);
        } else {
            v = make_float4(0.f, 0.f, 0.f, 0.f);
        }
        *(float4*)&g_y1[((b * MID + gc) * H + h0 + r) * W + w0 + cst] = v;
    }
}

// ---------------------------------------------------------------------------
// Fused Kernel 2+3: conv2(3x3) + BN + ReLU + mask  -->  conv3(1x1) + BN +
// residual + ReLU, per (tile, group) CTA, 256 threads. y2 never leaves smem.
//
// smem (floats): [0,3840) halo [32 ic][10 rows pad12]  (later y2 [32][64])
//                [3840,7936) w3 [32 ic][128 oc]
//                [7936,12544) w2 phase slab [16 ic][9 tap][32 oc]
// ---------------------------------------------------------------------------
#define SM_HALO  0
#define SM_W3    3840
#define SM_W2    7936
#define K23_SMEM (12544 * 4)

__global__ __launch_bounds__(256) void k23_fused(
    const float* __restrict__ x, const float* __restrict__ mask,
    const float* __restrict__ g2, const float* __restrict__ b2,
    const float* __restrict__ m2, const float* __restrict__ v2,
    const float* __restrict__ g3, const float* __restrict__ b3,
    const float* __restrict__ m3, const float* __restrict__ v3,
    float* __restrict__ out)
{
    const int bh = blockIdx.x / 7, bw = blockIdx.x % 7;
    const int g = blockIdx.y, b = blockIdx.z;
    const int h0 = bh * 8, w0 = bw * 8;
    const int t = threadIdx.x;
    const int pxq = t & 15;                 // 4-px quad (both phases)
    const int ocq2 = t >> 4;                // k2: [0,16) -> 2 oc
    const int ocp  = t >> 4;                // k3: [0,16) -> 8 oc
    const int r = pxq >> 1, cst = (pxq & 1) * 4;

    const float m = mask[((b * GRP + g) * MH + bh) * MW + bw];

    if (m == 0.0f) {
        // out = relu(bias3 + x) for this group's 128 oc x 64 px
        #pragma unroll
        for (int k = 0; k < 8; k++) {
            int gc = g * 128 + ocp * 8 + k;
            float sc = g3[gc] * rsqrtf(v3[gc] + EPSV);
            float bi = b3[gc] - m3[gc] * sc;
            long idx = ((long)(b * CIN + gc) * H + h0 + r) * W + w0 + cst;
            float4 xv = *(const float4*)&x[idx];
            float4 v;
            v.x = fmaxf(bi + xv.x, 0.0f);
            v.y = fmaxf(bi + xv.y, 0.0f);
            v.z = fmaxf(bi + xv.z, 0.0f);
            v.w = fmaxf(bi + xv.w, 0.0f);
            *(float4*)&out[idx] = v;
        }
        return;
    }

    extern __shared__ float sm[];

    // halo: 32 ic x 10x10, padded row stride 12 (y1 post-mask; zero borders)
    for (int i = t; i < 32 * 100; i += 256) {
        int ic = i / 100, p = i % 100;
        int pr = p / 10, pc = p % 10;
        int rr = h0 + pr - 1, c2 = w0 + pc - 1;
        float v = 0.0f;
        if (rr >= 0 && rr < H && c2 >= 0 && c2 < W)
            v = g_y1[((b * MID + g * 32 + ic) * H + rr) * W + c2];
        sm[SM_HALO + ic * 120 + pr * 12 + pc] = v;
    }
    // w3 slab: linear float4 copy
    {
        const float4* src = (const float4*)(tw3 + g * 4096);
        float4* dst = (float4*)(sm + SM_W3);
        #pragma unroll
        for (int j = 0; j < 4; j++)
            dst[t + j * 256] = src[t + j * 256];
    }
    // w2 phase 0
    {
        const float4* src = (const float4*)(tw2 + g * 9216);
        float4* dst = (float4*)(sm + SM_W2);
        #pragma unroll
        for (int j = 0; j < 5; j++) {
            int i = t + j * 256;
            if (i < 1152) dst[i] = src[i];
        }
    }
    __syncthreads();

    // ---- conv2: thread = 4 px x 2 oc ----
    float acc2[2][4];
    #pragma unroll
    for (int k = 0; k < 2; k++)
        #pragma unroll
        for (int q = 0; q < 4; q++) acc2[k][q] = 0.0f;

    for (int ph = 0; ph < 2; ph++) {
        if (ph) {
            __syncthreads();
            const float4* src = (const float4*)(tw2 + g * 9216 + 4608);
            float4* dst = (float4*)(sm + SM_W2);
            #pragma unroll
            for (int j = 0; j < 5; j++) {
                int i = t + j * 256;
                if (i < 1152) dst[i] = src[i];
            }
            __syncthreads();
        }
        #pragma unroll 4
        for (int icc = 0; icc < 16; icc++) {
            int ic = ph * 16 + icc;
            const float* hb = sm + SM_HALO + ic * 120;
            float xr[3][6];
            #pragma unroll
            for (int kr = 0; kr < 3; kr++) {
                float4 a = *(const float4*)&hb[(r + kr) * 12 + cst];
                float2 bq = *(const float2*)&hb[(r + kr) * 12 + cst + 4];
                xr[kr][0] = a.x; xr[kr][1] = a.y; xr[kr][2] = a.z; xr[kr][3] = a.w;
                xr[kr][4] = bq.x; xr[kr][5] = bq.y;
            }
            const float* wb = sm + SM_W2 + icc * 288;
            #pragma unroll
            for (int kr = 0; kr < 3; kr++) {
                #pragma unroll
                for (int kc = 0; kc < 3; kc++) {
                    float2 wv = *(const float2*)&wb[(kr * 3 + kc) * 32 + ocq2 * 2];
                    #pragma unroll
                    for (int q = 0; q < 4; q++) {
                        float xv = xr[kr][q + kc];
                        acc2[0][q] += wv.x * xv;
                        acc2[1][q] += wv.y * xv;
                    }
                }
            }
        }
    }

    // bn2 + relu (+mask==1), y2 tile -> smem (aliases dead halo)
    __syncthreads();
    #pragma unroll
    for (int k = 0; k < 2; k++) {
        int gc = g * 32 + ocq2 * 2 + k;
        float sc = g2[gc] * rsqrtf(v2[gc] + EPSV);
        float bi = b2[gc] - m2[gc] * sc;
        float4 v;
        v.x = fmaxf(acc2[k][0] * sc + bi, 0.0f);
        v.y = fmaxf(acc2[k][1] * sc + bi, 0.0f);
        v.z = fmaxf(acc2[k][2] * sc + bi, 0.0f);
        v.w = fmaxf(acc2[k][3] * sc + bi, 0.0f);
        *(float4*)&sm[SM_HALO + (ocq2 * 2 + k) * 64 + pxq * 4] = v;
    }
    __syncthreads();

    // ---- conv3: thread = 4 px x 8 oc ----
    float acc3[8][4];
    #pragma unroll
    for (int k = 0; k < 8; k++)
        #pragma unroll
        for (int q = 0; q < 4; q++) acc3[k][q] = 0.0f;

    const float* w3s = sm + SM_W3;
    #pragma unroll 4
    for (int ic = 0; ic < 32; ic++) {
        float4 xv = *(const float4*)&sm[SM_HALO + ic * 64 + pxq * 4];
        const float* wr = &w3s[ic * 128 + ocp * 8];
        float4 wa = *(const float4*)wr;
        float4 wb2 = *(const float4*)(wr + 4);
        float wk[8] = {wa.x, wa.y, wa.z, wa.w, wb2.x, wb2.y, wb2.z, wb2.w};
        #pragma unroll
        for (int k = 0; k < 8; k++) {
            acc3[k][0] += wk[k] * xv.x;
            acc3[k][1] += wk[k] * xv.y;
            acc3[k][2] += wk[k] * xv.z;
            acc3[k][3] += wk[k] * xv.w;
        }
    }

    #pragma unroll
    for (int k = 0; k < 8; k++) {
        int gc = g * 128 + ocp * 8 + k;
        float sc = g3[gc] * rsqrtf(v3[gc] + EPSV);
        float bi = b3[gc] - m3[gc] * sc;
        long idx = ((long)(b * CIN + gc) * H + h0 + r) * W + w0 + cst;
        float4 xv = *(const float4*)&x[idx];
        float4 v;
        v.x = fmaxf(acc3[k][0] * sc + bi + xv.x, 0.0f);
        v.y = fmaxf(acc3[k][1] * sc + bi + xv.y, 0.0f);
        v.z = fmaxf(acc3[k][2] * sc + bi + xv.z, 0.0f);
        v.w = fmaxf(acc3[k][3] * sc + bi + xv.w, 0.0f);
        *(float4*)&out[idx] = v;
    }
}

// ---------------------------------------------------------------------------
extern "C" void kernel_launch(void* const* d_in, const int* in_sizes, int n_in,
                              void* d_out, int out_size)
{
    const float* x    = (const float*)d_in[0];
    const float* mask = (const float*)d_in[1];
    const float* w1   = (const float*)d_in[2];
    const float* g1   = (const float*)d_in[3];
    const float* b1   = (const float*)d_in[4];
    const float* m1   = (const float*)d_in[5];
    const float* v1   = (const float*)d_in[6];
    const float* w2   = (const float*)d_in[7];
    const float* g2   = (const float*)d_in[8];
    const float* b2   = (const float*)d_in[9];
    const float* m2   = (const float*)d_in[10];
    const float* v2   = (const float*)d_in[11];
    const float* w3   = (const float*)d_in[12];
    const float* g3   = (const float*)d_in[13];
    const float* b3   = (const float*)d_in[14];
    const float* m3   = (const float*)d_in[15];
    const float* v3   = (const float*)d_in[16];
    float* out = (float*)d_out;

    cudaFuncSetAttribute(k23_fused, cudaFuncAttributeMaxDynamicSharedMemorySize, K23_SMEM);

    setup_tw<<<144, 256>>>(w1, w2, w3);
    dim3 grid1(49, 2, BATCH);
    k1_conv1<<<grid1, 256>>>(x, mask, g1, b1, m1, v1);
    dim3 grid2(49, GRP, BATCH);
    k23_fused<<<grid2, 256, K23_SMEM>>>(x, mask, g2, b2, m2, v2,
                                        g3, b3, m3, v3, out);
}